// round 15
// baseline (speedup 1.0000x reference)
#include <cuda_runtime.h>
#include <cuda_bf16.h>
#include <cuda_fp8.h>
#include <cstdint>

// Problem constants
#define N_B    32
#define C_DIM  512
#define T_DIM  1024
#define D_DIM  512
#define K_CODES 1024
#define M_ROWS 32768

// Output layout (concatenation of reference return tuple, fp32)
#define O_ZQST   0UL
#define O_COMMIT 16777216UL
#define O_SOM    16777217UL
#define O_NB     16777218UL
#define O_DIST   100663298UL
#define O_K      134217730UL

#define NUM_GATHER_BLOCKS 2048    // 32 n * 64 t-tiles

// ---------------- scratch (device globals; no allocations) ----------------
static __device__ float g_zsq[M_ROWS];
static __device__ float g_zsqp[8][M_ROWS];
static __device__ float g_esq[K_CODES];
static __device__ int   g_k[M_ROWS];
static __device__ unsigned long long g_bmin[M_ROWS][8];   // per-(row, n-block) min key
static __device__ float g_cpart[NUM_GATHER_BLOCKS];
static __device__ float g_spart[NUM_GATHER_BLOCKS];

// fp8 operands + contiguous fp32 transposed z (for fixup / gather)
static __device__ uint8_t g_z8[M_ROWS * D_DIM];
static __device__ uint8_t g_e8[K_CODES * D_DIM];
static __device__ float g_zt[M_ROWS * D_DIM];

// ---------------- PTX helpers (baseline sm_80/89 PTX, valid on compute_103) ----
__device__ __forceinline__ void cp16(uint32_t dst, const void* src) {
    asm volatile("cp.async.cg.shared.global [%0], [%1], 16;" :: "r"(dst), "l"(src));
}
#define CP_COMMIT() asm volatile("cp.async.commit_group;" ::: "memory")
#define CP_WAIT1()  asm volatile("cp.async.wait_group 1;" ::: "memory")

#define LDSM4(r0, r1, r2, r3, addr)                                        \
    asm volatile("ldmatrix.sync.aligned.m8n8.x4.shared.b16 {%0,%1,%2,%3}, [%4];" \
                 : "=r"(r0), "=r"(r1), "=r"(r2), "=r"(r3) : "r"(addr))

// fp8 m16n8k32: fragments byte-compatible with bf16 m16n8k16 (b16-pair view)
__device__ __forceinline__ void mma16832(float* c, const uint32_t* a, const uint32_t* b) {
    asm volatile(
        "mma.sync.aligned.m16n8k32.row.col.f32.e4m3.e4m3.f32 "
        "{%0,%1,%2,%3}, {%4,%5,%6,%7}, {%8,%9}, {%0,%1,%2,%3};"
        : "+f"(c[0]), "+f"(c[1]), "+f"(c[2]), "+f"(c[3])
        : "r"(a[0]), "r"(a[1]), "r"(a[2]), "r"(a[3]), "r"(b[0]), "r"(b[1]));
}

__device__ __forceinline__ uint8_t to_e4m3(float v) {
    return (uint8_t)__nv_cvt_float_to_fp8(v, __NV_SATFINITE, __NV_E4M3);
}

// ---------------------------------------------------------------------------
// Prep: transpose x -> z rows (m-major), fp8 + fp32 copies + zsq partials
// ---------------------------------------------------------------------------
__global__ void prep_z_kernel(const float* __restrict__ x) {
    __shared__ float s[64][33];
    int tid = threadIdx.x;
    int t0 = blockIdx.x * 32, d0 = blockIdx.y * 64, n = blockIdx.z;
    const float* xp = x + (size_t)n * C_DIM * T_DIM + (size_t)d0 * T_DIM + t0;
#pragma unroll
    for (int w = 0; w < 8; w++) {
        int idx = tid + w * 256;
        s[idx >> 5][idx & 31] = xp[(size_t)(idx >> 5) * T_DIM + (idx & 31)];
    }
    __syncthreads();
#pragma unroll
    for (int w = 0; w < 4; w++) {
        int idx = tid + w * 256;
        int dp = idx & 31, tt = idx >> 5;
        int m = n * T_DIM + t0 + tt;
        size_t o = (size_t)m * 256 + (d0 >> 1) + dp;   // uchar2 units
        float v0 = s[2 * dp][tt];
        float v1 = s[2 * dp + 1][tt];
        uchar2 p8;
        p8.x = to_e4m3(v0);
        p8.y = to_e4m3(v1);
        ((uchar2*)g_z8)[o] = p8;
        float2 zf; zf.x = v0; zf.y = v1;
        *(float2*)(g_zt + (size_t)m * 512 + d0 + 2 * dp) = zf;
    }
    if (tid < 32) {
        float acc = 0.f;
#pragma unroll
        for (int d = 0; d < 64; d++) {
            float v = s[d][tid];
            acc += v * v;
        }
        g_zsqp[d0 >> 6][n * T_DIM + t0 + tid] = acc;
    }
}

// esq (+ fp8 convert of E) for blocks 0..1023; zsq combine for blocks 1024..1151
__global__ void esq_zsq_kernel(const float* __restrict__ E) {
    __shared__ float red[256];
    int b = blockIdx.x;
    int tid = threadIdx.x;
    if (b < K_CODES) {
        const float* e = E + (size_t)b * D_DIM;
        float acc = 0.f;
#pragma unroll
        for (int q = 0; q < 2; q++) {
            int d = tid + q * 256;
            float v = e[d];
            g_e8[(size_t)b * D_DIM + d] = to_e4m3(v);
            acc += v * v;
        }
        red[tid] = acc;
        __syncthreads();
        for (int s = 128; s > 0; s >>= 1) {
            if (tid < s) red[tid] += red[tid + s];
            __syncthreads();
        }
        if (tid == 0) g_esq[b] = red[0];
    } else {
        int m = (b - K_CODES) * 256 + tid;
        float acc = 0.f;
#pragma unroll
        for (int q = 0; q < 8; q++) acc += g_zsqp[q][m];
        g_zsq[m] = acc;
    }
}

// ---------------------------------------------------------------------------
// Distance GEMM via mma.sync fp8 e4m3 (m16n8k32). Same pipeline as the proven
// bf16 R11/R13 kernel: 2 CTAs/SM, 2x4 warps, 64x32 warp tiles, 3-stage
// cp.async, KSTRIDE=144 (128B data rows). KITERS halves to 4 (K=512 fp8 =
// 4 stages of 128 elements). LDSM addressing identical (b16-pair view).
// ---------------------------------------------------------------------------
#define BM 128
#define BN 128
#define KSTRIDE 144                        // 128B data + 16B pad (conflict-free)
#define STAGE_BYTES (2 * BM * KSTRIDE)     // 36864
#define NSTAGES 3
#define DYN_SMEM (NSTAGES * STAGE_BYTES)   // 110592 (2 CTAs/SM: 221KB)
#define KITERS 4                           // 4 x 128 fp8 elements = K 512

__device__ __forceinline__ void load_stage(
    uint32_t sbase, int tid, int m0, int n0, int it)
{
    int k0 = it * 128;                     // bytes == elements (fp8)
#pragma unroll
    for (int q = 0; q < 4; q++) {
        int ch = tid + q * 256;
        int row = ch >> 3, c = ch & 7;
        cp16(sbase + row * KSTRIDE + c * 16,
             g_z8 + (size_t)(m0 + row) * 512 + k0 + c * 16);
    }
#pragma unroll
    for (int q = 0; q < 4; q++) {
        int ch = tid + q * 256;
        int row = ch >> 3, c = ch & 7;
        cp16(sbase + BM * KSTRIDE + row * KSTRIDE + c * 16,
             g_e8 + (size_t)(n0 + row) * 512 + k0 + c * 16);
    }
    CP_COMMIT();
}

__global__ __launch_bounds__(256, 2) void mma_dist_kernel(float* __restrict__ out) {
    extern __shared__ char sm[];
    uint32_t smb;
    asm("{ .reg .u64 t; cvta.to.shared.u64 t, %1; cvt.u32.u64 %0, t; }"
        : "=r"(smb) : "l"(sm));

    int tid = threadIdx.x, lane = tid & 31, wid = tid >> 5;
    int wm = wid >> 2, wn = wid & 3;
    int n0 = blockIdx.x * BN, m0 = blockIdx.y * BM;

    int t8 = lane >> 3, lr = lane & 7;
    uint32_t offA[4], offB[2];             // ks=0 base; +ks*32 bytes per k32 step
#pragma unroll
    for (int mt = 0; mt < 4; mt++) {
        int row = wm * 64 + mt * 16 + (t8 & 1) * 8 + lr;
        int col = (t8 >> 1) * 8;           // b16 cols (= 2 fp8 each)
        offA[mt] = row * KSTRIDE + col * 2;
    }
#pragma unroll
    for (int np = 0; np < 2; np++) {
        int row = wn * 32 + np * 16 + (t8 >> 1) * 8 + lr;
        int col = (t8 & 1) * 8;
        offB[np] = BM * KSTRIDE + row * KSTRIDE + col * 2;
    }

    float acc[4][4][4];
#pragma unroll
    for (int i = 0; i < 4; i++)
#pragma unroll
        for (int j = 0; j < 4; j++)
#pragma unroll
            for (int q = 0; q < 4; q++) acc[i][j][q] = 0.f;

    load_stage(smb + 0 * STAGE_BYTES, tid, m0, n0, 0);
    load_stage(smb + 1 * STAGE_BYTES, tid, m0, n0, 1);

    for (int it = 0; it < KITERS; it++) {
        CP_WAIT1();
        __syncthreads();
        int nx = it + NSTAGES - 1;
        if (nx < KITERS)
            load_stage(smb + (nx % 3) * STAGE_BYTES, tid, m0, n0, nx);
        else
            CP_COMMIT();
        uint32_t sbase = smb + (it % 3) * STAGE_BYTES;
#pragma unroll
        for (int ks = 0; ks < 4; ks++) {   // 4 k32-steps per 128-elem stage
            uint32_t a[4][4], b[4][2];
#pragma unroll
            for (int mt = 0; mt < 4; mt++)
                LDSM4(a[mt][0], a[mt][1], a[mt][2], a[mt][3],
                      sbase + offA[mt] + ks * 32);
#pragma unroll
            for (int np = 0; np < 2; np++)
                LDSM4(b[2 * np][0], b[2 * np][1], b[2 * np + 1][0], b[2 * np + 1][1],
                      sbase + offB[np] + ks * 32);
#pragma unroll
            for (int mt = 0; mt < 4; mt++)
#pragma unroll
                for (int nt = 0; nt < 4; nt++)
                    mma16832(acc[mt][nt], a[mt], b[nt]);
        }
    }

    // ---------------- epilogue ----------------
    __syncthreads();
    unsigned long long* keyrow = (unsigned long long*)sm;   // [128][4]

#pragma unroll
    for (int mt = 0; mt < 4; mt++) {
#pragma unroll
        for (int half = 0; half < 2; half++) {
            int rl = wm * 64 + mt * 16 + half * 8 + (lane >> 2);
            int row = m0 + rl;
            float zr = g_zsq[row];
            float best = 3.4e38f;
            int bi = 0;
#pragma unroll
            for (int nt = 0; nt < 4; nt++) {
                int col = n0 + wn * 32 + nt * 8 + (lane & 3) * 2;
                float d0 = fmaf(-2.f, acc[mt][nt][half * 2 + 0], zr) + g_esq[col];
                float d1 = fmaf(-2.f, acc[mt][nt][half * 2 + 1], zr) + g_esq[col + 1];
                float2 st; st.x = d0; st.y = d1;
                __stcs((float2*)(out + O_DIST + (size_t)row * K_CODES + col), st);
                if (d0 < best) { best = d0; bi = col; }
                if (d1 < best) { best = d1; bi = col + 1; }
            }
            unsigned long long key =
                ((unsigned long long)__float_as_uint(best) << 32) | (unsigned)bi;
#pragma unroll
            for (int ofs = 1; ofs <= 2; ofs <<= 1) {
                unsigned long long o = __shfl_xor_sync(0xffffffffu, key, ofs);
                if (o < key) key = o;
            }
            if ((lane & 3) == 0) keyrow[rl * 4 + wn] = key;
        }
    }
    __syncthreads();
    if (tid < 128) {
        unsigned long long k0 = keyrow[tid * 4 + 0];
        unsigned long long k1 = keyrow[tid * 4 + 1];
        unsigned long long k2 = keyrow[tid * 4 + 2];
        unsigned long long k3 = keyrow[tid * 4 + 3];
        if (k1 < k0) k0 = k1;
        if (k2 < k0) k0 = k2;
        if (k3 < k0) k0 = k3;
        g_bmin[m0 + tid][blockIdx.x] = k0;
    }
}

// ---------------------------------------------------------------------------
// Fixup: EPS = 1.5 (~7 sigma of fp8 dist error diff, flip prob ~1e-11/row).
// Scan only blocks whose min is within EPS of global min; candidates get an
// fp32 dot + reference-mimicking fp32 assembly; ties -> lower index.
// ---------------------------------------------------------------------------
#define FIX_EPS 1.5f
#define MAXCAND 128

__global__ __launch_bounds__(256) void fixup_kernel(const float* __restrict__ E,
                                                    float* __restrict__ out) {
    __shared__ int s_cnt[8];
    __shared__ int s_cand[8][MAXCAND];
    int w = threadIdx.x >> 5, lane = threadIdx.x & 31;
    int m = blockIdx.x * 8 + w;
    if (lane == 0) s_cnt[w] = 0;
    __syncwarp();

    unsigned long long mykey = (lane < 8) ? g_bmin[m][lane] : 0xFFFFFFFFFFFFFFFFull;
    unsigned long long gmin = mykey;
#pragma unroll
    for (int ofs = 16; ofs > 0; ofs >>= 1) {
        unsigned long long o = __shfl_xor_sync(0xffffffffu, gmin, ofs);
        if (o < gmin) gmin = o;
    }
    float thr = __uint_as_float((unsigned)(gmin >> 32)) + FIX_EPS;
    const float* drow = out + O_DIST + (size_t)m * K_CODES;

#pragma unroll
    for (int b = 0; b < 8; b++) {
        unsigned long long kb = __shfl_sync(0xffffffffu, mykey, b);
        if (__uint_as_float((unsigned)(kb >> 32)) <= thr) {
            int c = b * 128 + lane;
#pragma unroll
            for (int q = 0; q < 4; q++, c += 32) {
                if (__ldcs(&drow[c]) <= thr) {
                    int p = atomicAdd(&s_cnt[w], 1);
                    if (p < MAXCAND) s_cand[w][p] = c;
                }
            }
        }
    }
    __syncwarp();
    int ncand = min(s_cnt[w], MAXCAND);

    int bi;
    if (ncand == 1) {
        bi = s_cand[w][0];
    } else {
        const float* zrow = g_zt + (size_t)m * 512;
        float zc[16];
#pragma unroll
        for (int q = 0; q < 16; q++) zc[q] = zrow[lane + q * 32];
        float zsq_m = g_zsq[m];
        float bd = 3.4e38f;
        bi = 0x7FFFFFFF;
        for (int j = 0; j < ncand; j++) {
            int c = s_cand[w][j];
            const float* e = E + (size_t)c * 512;
            float s = 0.f;
#pragma unroll
            for (int q = 0; q < 16; q++)
                s = fmaf(zc[q], e[lane + q * 32], s);
#pragma unroll
            for (int ofs = 16; ofs > 0; ofs >>= 1)
                s += __shfl_xor_sync(0xffffffffu, s, ofs);
            float t1 = zsq_m - 2.0f * s;
            float d = t1 + g_esq[c];
            if (d < bd || (d == bd && c < bi)) { bd = d; bi = c; }
        }
    }
    if (lane == 0) {
        g_k[m] = bi;
        out[O_K + m] = (float)bi;
    }
}

// ---------------------------------------------------------------------------
// Gather neighbors + z_q_st + loss partials. 512 threads, 16-t tile,
// 2048 blocks (4 CTAs/SM). R12/R13-proven config, unchanged.
// ---------------------------------------------------------------------------
#define SG_STRIDE 514
#define GATHER_SMEM (16 * SG_STRIDE * 4)   // 32896 bytes

__global__ __launch_bounds__(512) void gather_kernel(const float* __restrict__ E,
                                                     float* __restrict__ out)
{
    extern __shared__ float s[];           // [16 t][SG_STRIDE]
    __shared__ int   s_code[16][5];
    __shared__ float s_mask[16][5];
    __shared__ float red[512];

    int tid = threadIdx.x;
    int dq = tid & 255;
    int tg = tid >> 8;                     // 0..1, 8 t each
    int n = blockIdx.y;
    int t0 = blockIdx.x * 16;

    if (tid < 16) {
        int m = n * T_DIM + t0 + tid;
        int kk = g_k[m];
        int k1 = kk >> 5, k2 = kk & 31;
        s_code[tid][0] = kk;                 s_mask[tid][0] = 1.f;
        s_code[tid][1] = (k1 + 1) * 32 + k2; s_mask[tid][1] = (k1 < 31) ? 1.f : 0.f;
        s_code[tid][2] = (k1 - 1) * 32 + k2; s_mask[tid][2] = (k1 > 0)  ? 1.f : 0.f;
        s_code[tid][3] = kk + 1;             s_mask[tid][3] = (k2 < 31) ? 1.f : 0.f;
        s_code[tid][4] = kk - 1;             s_mask[tid][4] = (k2 > 0)  ? 1.f : 0.f;
    }
    __syncthreads();

    float cacc = 0.f, sacc = 0.f;
    for (int i = 0; i < 8; i++) {
        int t = tg * 8 + i;
        int m = n * T_DIM + t0 + t;
        float2 ze = *(const float2*)(g_zt + (size_t)m * 512 + dq * 2);
        float* nbp = out + O_NB + (size_t)m * (5 * 512);
        float2 zq = *(const float2*)(E + (size_t)s_code[t][0] * 512 + dq * 2);
        __stcs((float2*)(nbp + dq * 2), zq);
        float dx = zq.x - ze.x, dy = zq.y - ze.y;
        cacc += dx * dx + dy * dy;
        sacc += dx * dx + dy * dy;
        *(float2*)&s[t * SG_STRIDE + dq * 2] = zq;
#pragma unroll
        for (int slot = 1; slot < 5; slot++) {
            float2 v;
            if (s_mask[t][slot] != 0.f)
                v = *(const float2*)(E + (size_t)s_code[t][slot] * 512 + dq * 2);
            else { v.x = 0.f; v.y = 0.f; }
            __stcs((float2*)(nbp + slot * 512 + dq * 2), v);
            float ax = ze.x - v.x, ay = ze.y - v.y;
            sacc += ax * ax + ay * ay;
        }
    }
    __syncthreads();

    // z_q_st[n, d, t0+4tq .. +3] float4 stores (16 t = 4 quads)
    {
        int tq = tid & 3;
        int dg = tid >> 2;                 // 0..127
        for (int d = dg; d < 512; d += 128) {
            float4 v;
            v.x = s[(4 * tq + 0) * SG_STRIDE + d];
            v.y = s[(4 * tq + 1) * SG_STRIDE + d];
            v.z = s[(4 * tq + 2) * SG_STRIDE + d];
            v.w = s[(4 * tq + 3) * SG_STRIDE + d];
            __stcs((float4*)&out[O_ZQST + (size_t)n * C_DIM * T_DIM
                                 + (size_t)d * T_DIM + t0 + 4 * tq], v);
        }
    }

    red[tid] = cacc;
    __syncthreads();
    for (int sft = 256; sft > 0; sft >>= 1) {
        if (tid < sft) red[tid] += red[tid + sft];
        __syncthreads();
    }
    float cblock = red[0];
    __syncthreads();
    red[tid] = sacc;
    __syncthreads();
    for (int sft = 256; sft > 0; sft >>= 1) {
        if (tid < sft) red[tid] += red[tid + sft];
        __syncthreads();
    }
    if (tid == 0) {
        int bid = blockIdx.y * gridDim.x + blockIdx.x;
        g_cpart[bid] = cblock;
        g_spart[bid] = red[0];
    }
}

__global__ void loss_kernel(float* __restrict__ out) {
    __shared__ double rc[256], rs[256];
    int tid = threadIdx.x;
    double c = 0.0, s = 0.0;
    for (int i = tid; i < NUM_GATHER_BLOCKS; i += 256) {
        c += (double)g_cpart[i];
        s += (double)g_spart[i];
    }
    rc[tid] = c; rs[tid] = s;
    __syncthreads();
    for (int sft = 128; sft > 0; sft >>= 1) {
        if (tid < sft) { rc[tid] += rc[tid + sft]; rs[tid] += rs[tid + sft]; }
        __syncthreads();
    }
    if (tid == 0) {
        double MD = (double)M_ROWS * (double)D_DIM;
        out[O_COMMIT] = (float)(2.0 * rc[0] / MD);
        out[O_SOM]    = (float)(rs[0] / (MD * 5.0));
    }
}

// ---------------------------------------------------------------------------
extern "C" void kernel_launch(void* const* d_in, const int* in_sizes, int n_in,
                              void* d_out, int out_size) {
    const float* x = (const float*)d_in[0];
    const float* E = (const float*)d_in[1];
    float* out = (float*)d_out;

    static int init = 0;
    if (!init) {
        cudaFuncSetAttribute(mma_dist_kernel,
                             cudaFuncAttributeMaxDynamicSharedMemorySize, DYN_SMEM);
        cudaFuncSetAttribute(gather_kernel,
                             cudaFuncAttributeMaxDynamicSharedMemorySize, GATHER_SMEM);
        init = 1;
    }

    dim3 gz(T_DIM / 32, C_DIM / 64, N_B);
    prep_z_kernel<<<gz, 256>>>(x);
    esq_zsq_kernel<<<K_CODES + M_ROWS / 256, 256>>>(E);
    dim3 gd(K_CODES / BN, M_ROWS / BM);
    mma_dist_kernel<<<gd, 256, DYN_SMEM>>>(out);
    fixup_kernel<<<M_ROWS / 8, 256>>>(E, out);
    dim3 g(T_DIM / 16, N_B);
    gather_kernel<<<g, 512, GATHER_SMEM>>>(E, out);
    loss_kernel<<<1, 256>>>(out);
}

// round 16
// speedup vs baseline: 1.2281x; 1.2281x over previous
#include <cuda_runtime.h>
#include <cuda_bf16.h>
#include <cstdint>

// Problem constants
#define N_B    32
#define C_DIM  512
#define T_DIM  1024
#define D_DIM  512
#define K_CODES 1024
#define M_ROWS 32768

// Output layout (concatenation of reference return tuple, fp32)
#define O_ZQST   0UL
#define O_COMMIT 16777216UL
#define O_SOM    16777217UL
#define O_NB     16777218UL
#define O_DIST   100663298UL
#define O_K      134217730UL

#define NUM_GATHER_BLOCKS 2048    // 32 n * 64 t-tiles

// ---------------- scratch (device globals; no allocations) ----------------
static __device__ float g_zsq[M_ROWS];
static __device__ float g_zsqp[8][M_ROWS];
static __device__ float g_esq[K_CODES];
static __device__ unsigned long long g_bmin[M_ROWS][8];   // per-(row, n-block) min key
static __device__ float g_cpart[NUM_GATHER_BLOCKS];
static __device__ float g_spart[NUM_GATHER_BLOCKS];

// bf16 operands + contiguous fp32 transposed z (for fixup / gather)
static __device__ __nv_bfloat16 g_z1[M_ROWS * D_DIM];
static __device__ __nv_bfloat16 g_e1[K_CODES * D_DIM];
static __device__ float g_zt[M_ROWS * D_DIM];

// ---------------- PTX helpers (baseline sm_80+ PTX, valid on compute_103) ----
__device__ __forceinline__ void cp16(uint32_t dst, const void* src) {
    asm volatile("cp.async.cg.shared.global [%0], [%1], 16;" :: "r"(dst), "l"(src));
}
#define CP_COMMIT() asm volatile("cp.async.commit_group;" ::: "memory")
#define CP_WAIT1()  asm volatile("cp.async.wait_group 1;" ::: "memory")

#define LDSM4(r0, r1, r2, r3, addr)                                        \
    asm volatile("ldmatrix.sync.aligned.m8n8.x4.shared.b16 {%0,%1,%2,%3}, [%4];" \
                 : "=r"(r0), "=r"(r1), "=r"(r2), "=r"(r3) : "r"(addr))

__device__ __forceinline__ void mma16816(float* c, const uint32_t* a, const uint32_t* b) {
    asm volatile(
        "mma.sync.aligned.m16n8k16.row.col.f32.bf16.bf16.f32 "
        "{%0,%1,%2,%3}, {%4,%5,%6,%7}, {%8,%9}, {%0,%1,%2,%3};"
        : "+f"(c[0]), "+f"(c[1]), "+f"(c[2]), "+f"(c[3])
        : "r"(a[0]), "r"(a[1]), "r"(a[2]), "r"(a[3]), "r"(b[0]), "r"(b[1]));
}

// ---------------------------------------------------------------------------
// Prep: transpose x -> z rows (m-major), bf16 + fp32 copies + zsq partials
// ---------------------------------------------------------------------------
__global__ void prep_z_kernel(const float* __restrict__ x) {
    __shared__ float s[64][33];
    int tid = threadIdx.x;
    int t0 = blockIdx.x * 32, d0 = blockIdx.y * 64, n = blockIdx.z;
    const float* xp = x + (size_t)n * C_DIM * T_DIM + (size_t)d0 * T_DIM + t0;
#pragma unroll
    for (int w = 0; w < 8; w++) {
        int idx = tid + w * 256;
        s[idx >> 5][idx & 31] = xp[(size_t)(idx >> 5) * T_DIM + (idx & 31)];
    }
    __syncthreads();
#pragma unroll
    for (int w = 0; w < 4; w++) {
        int idx = tid + w * 256;
        int dp = idx & 31, tt = idx >> 5;
        int m = n * T_DIM + t0 + tt;
        size_t o = (size_t)m * 256 + (d0 >> 1) + dp;
        float v0 = s[2 * dp][tt];
        float v1 = s[2 * dp + 1][tt];
        __nv_bfloat162 p1;
        p1.x = __float2bfloat16_rn(v0);
        p1.y = __float2bfloat16_rn(v1);
        ((__nv_bfloat162*)g_z1)[o] = p1;
        float2 zf; zf.x = v0; zf.y = v1;
        *(float2*)(g_zt + (size_t)m * 512 + d0 + 2 * dp) = zf;
    }
    if (tid < 32) {
        float acc = 0.f;
#pragma unroll
        for (int d = 0; d < 64; d++) {
            float v = s[d][tid];
            acc += v * v;
        }
        g_zsqp[d0 >> 6][n * T_DIM + t0 + tid] = acc;
    }
}

// esq (+ bf16 convert of E) for blocks 0..1023; zsq combine for blocks 1024..1151
__global__ void esq_zsq_kernel(const float* __restrict__ E) {
    __shared__ float red[256];
    int b = blockIdx.x;
    int tid = threadIdx.x;
    if (b < K_CODES) {
        const float* e = E + (size_t)b * D_DIM;
        float acc = 0.f;
#pragma unroll
        for (int q = 0; q < 2; q++) {
            int d = tid + q * 256;
            float v = e[d];
            g_e1[(size_t)b * D_DIM + d] = __float2bfloat16_rn(v);
            acc += v * v;
        }
        red[tid] = acc;
        __syncthreads();
        for (int s = 128; s > 0; s >>= 1) {
            if (tid < s) red[tid] += red[tid + s];
            __syncthreads();
        }
        if (tid == 0) g_esq[b] = red[0];
    } else {
        int m = (b - K_CODES) * 256 + tid;
        float acc = 0.f;
#pragma unroll
        for (int q = 0; q < 8; q++) acc += g_zsqp[q][m];
        g_zsq[m] = acc;
    }
}

// ---------------------------------------------------------------------------
// Distance GEMM via mma.sync (HMMA bf16), R11/R13/R14-proven structure:
// 2 CTAs/SM, 2x4 warps, 64x32 warp tiles, BK=64, 3-stage cp.async. UNCHANGED.
// ---------------------------------------------------------------------------
#define BM 128
#define BN 128
#define BK 64
#define KSTRIDE 144                        // 128B data + 16B pad (conflict-free)
#define STAGE_BYTES (2 * BM * KSTRIDE)     // 36864
#define NSTAGES 3
#define DYN_SMEM (NSTAGES * STAGE_BYTES)   // 110592 (2 CTAs/SM: 221KB)
#define KITERS 8

__device__ __forceinline__ void load_stage(
    uint32_t sbase, int tid, int m0, int n0, int it)
{
    int k0 = it * BK;
#pragma unroll
    for (int q = 0; q < 4; q++) {
        int ch = tid + q * 256;
        int row = ch >> 3, c = ch & 7;
        cp16(sbase + row * KSTRIDE + c * 16,
             g_z1 + (size_t)(m0 + row) * 512 + k0 + c * 8);
    }
#pragma unroll
    for (int q = 0; q < 4; q++) {
        int ch = tid + q * 256;
        int row = ch >> 3, c = ch & 7;
        cp16(sbase + BM * KSTRIDE + row * KSTRIDE + c * 16,
             g_e1 + (size_t)(n0 + row) * 512 + k0 + c * 8);
    }
    CP_COMMIT();
}

__global__ __launch_bounds__(256, 2) void mma_dist_kernel(float* __restrict__ out) {
    extern __shared__ char sm[];
    uint32_t smb;
    asm("{ .reg .u64 t; cvta.to.shared.u64 t, %1; cvt.u32.u64 %0, t; }"
        : "=r"(smb) : "l"(sm));

    int tid = threadIdx.x, lane = tid & 31, wid = tid >> 5;
    int wm = wid >> 2, wn = wid & 3;
    int n0 = blockIdx.x * BN, m0 = blockIdx.y * BM;

    int t8 = lane >> 3, lr = lane & 7;
    uint32_t offA[4], offB[2];
#pragma unroll
    for (int mt = 0; mt < 4; mt++) {
        int row = wm * 64 + mt * 16 + (t8 & 1) * 8 + lr;
        int col = (t8 >> 1) * 8;
        offA[mt] = row * KSTRIDE + col * 2;
    }
#pragma unroll
    for (int np = 0; np < 2; np++) {
        int row = wn * 32 + np * 16 + (t8 >> 1) * 8 + lr;
        int col = (t8 & 1) * 8;
        offB[np] = BM * KSTRIDE + row * KSTRIDE + col * 2;
    }

    float acc[4][4][4];
#pragma unroll
    for (int i = 0; i < 4; i++)
#pragma unroll
        for (int j = 0; j < 4; j++)
#pragma unroll
            for (int q = 0; q < 4; q++) acc[i][j][q] = 0.f;

    load_stage(smb + 0 * STAGE_BYTES, tid, m0, n0, 0);
    load_stage(smb + 1 * STAGE_BYTES, tid, m0, n0, 1);

    for (int it = 0; it < KITERS; it++) {
        CP_WAIT1();
        __syncthreads();
        int nx = it + NSTAGES - 1;
        if (nx < KITERS)
            load_stage(smb + (nx % 3) * STAGE_BYTES, tid, m0, n0, nx);
        else
            CP_COMMIT();
        uint32_t sbase = smb + (it % 3) * STAGE_BYTES;
#pragma unroll
        for (int ks = 0; ks < 4; ks++) {
            uint32_t a[4][4], b[4][2];
#pragma unroll
            for (int mt = 0; mt < 4; mt++)
                LDSM4(a[mt][0], a[mt][1], a[mt][2], a[mt][3],
                      sbase + offA[mt] + ks * 32);
#pragma unroll
            for (int np = 0; np < 2; np++)
                LDSM4(b[2 * np][0], b[2 * np][1], b[2 * np + 1][0], b[2 * np + 1][1],
                      sbase + offB[np] + ks * 32);
#pragma unroll
            for (int mt = 0; mt < 4; mt++)
#pragma unroll
                for (int nt = 0; nt < 4; nt++)
                    mma16816(acc[mt][nt], a[mt], b[nt]);
        }
    }

    // ---------------- epilogue ----------------
    __syncthreads();
    unsigned long long* keyrow = (unsigned long long*)sm;   // [128][4]

#pragma unroll
    for (int mt = 0; mt < 4; mt++) {
#pragma unroll
        for (int half = 0; half < 2; half++) {
            int rl = wm * 64 + mt * 16 + half * 8 + (lane >> 2);
            int row = m0 + rl;
            float zr = g_zsq[row];
            float best = 3.4e38f;
            int bi = 0;
#pragma unroll
            for (int nt = 0; nt < 4; nt++) {
                int col = n0 + wn * 32 + nt * 8 + (lane & 3) * 2;
                float d0 = fmaf(-2.f, acc[mt][nt][half * 2 + 0], zr) + g_esq[col];
                float d1 = fmaf(-2.f, acc[mt][nt][half * 2 + 1], zr) + g_esq[col + 1];
                float2 st; st.x = d0; st.y = d1;
                __stcs((float2*)(out + O_DIST + (size_t)row * K_CODES + col), st);
                if (d0 < best) { best = d0; bi = col; }
                if (d1 < best) { best = d1; bi = col + 1; }
            }
            unsigned long long key =
                ((unsigned long long)__float_as_uint(best) << 32) | (unsigned)bi;
#pragma unroll
            for (int ofs = 1; ofs <= 2; ofs <<= 1) {
                unsigned long long o = __shfl_xor_sync(0xffffffffu, key, ofs);
                if (o < key) key = o;
            }
            if ((lane & 3) == 0) keyrow[rl * 4 + wn] = key;
        }
    }
    __syncthreads();
    if (tid < 128) {
        unsigned long long k0 = keyrow[tid * 4 + 0];
        unsigned long long k1 = keyrow[tid * 4 + 1];
        unsigned long long k2 = keyrow[tid * 4 + 2];
        unsigned long long k3 = keyrow[tid * 4 + 3];
        if (k1 < k0) k0 = k1;
        if (k2 < k0) k0 = k2;
        if (k3 < k0) k0 = k3;
        g_bmin[m0 + tid][blockIdx.x] = k0;
    }
}

// ---------------------------------------------------------------------------
// Gather + INLINE FIXUP. 512 threads = 16 warps; block owns 16 rows (one t-tile).
// Phase 1: warp w resolves row w's argmin (R14 fixup logic: block-min keys ->
// threshold EPS=0.1 -> candidate scan -> fp32 re-dot, ties -> lower index),
// writes out[O_K+m] and fills s_code/s_mask directly. Phase 2: gather (R14).
// ---------------------------------------------------------------------------
#define FIX_EPS 0.1f
#define MAXCAND 64
#define SG_STRIDE 514
#define GATHER_SMEM (16 * SG_STRIDE * 4)   // 32896 bytes

__global__ __launch_bounds__(512) void gather_kernel(const float* __restrict__ E,
                                                     float* __restrict__ out)
{
    extern __shared__ float s[];           // [16 t][SG_STRIDE]
    __shared__ int   s_code[16][5];
    __shared__ float s_mask[16][5];
    __shared__ float red[512];
    __shared__ int   s_cnt[16];
    __shared__ int   s_cand[16][MAXCAND];

    int tid = threadIdx.x;
    int lane = tid & 31;
    int w = tid >> 5;                      // warp = row within tile
    int n = blockIdx.y;
    int t0 = blockIdx.x * 16;

    // ---------------- phase 1: per-row argmin fixup ----------------
    {
        int m = n * T_DIM + t0 + w;
        if (lane == 0) s_cnt[w] = 0;
        __syncwarp();

        unsigned long long mykey = (lane < 8) ? g_bmin[m][lane]
                                              : 0xFFFFFFFFFFFFFFFFull;
        unsigned long long gmin = mykey;
#pragma unroll
        for (int ofs = 16; ofs > 0; ofs >>= 1) {
            unsigned long long o = __shfl_xor_sync(0xffffffffu, gmin, ofs);
            if (o < gmin) gmin = o;
        }
        float thr = __uint_as_float((unsigned)(gmin >> 32)) + FIX_EPS;
        const float* drow = out + O_DIST + (size_t)m * K_CODES;

#pragma unroll
        for (int b = 0; b < 8; b++) {
            unsigned long long kb = __shfl_sync(0xffffffffu, mykey, b);
            if (__uint_as_float((unsigned)(kb >> 32)) <= thr) {
                int c = b * 128 + lane;
#pragma unroll
                for (int q = 0; q < 4; q++, c += 32) {
                    if (__ldcs(&drow[c]) <= thr) {
                        int p = atomicAdd(&s_cnt[w], 1);
                        if (p < MAXCAND) s_cand[w][p] = c;
                    }
                }
            }
        }
        __syncwarp();
        int ncand = min(s_cnt[w], MAXCAND);

        int bi;
        if (ncand == 1) {
            bi = s_cand[w][0];
        } else {
            const float* zrow = g_zt + (size_t)m * 512;
            float zc[16];
#pragma unroll
            for (int q = 0; q < 16; q++) zc[q] = zrow[lane + q * 32];
            float zsq_m = g_zsq[m];
            float bd = 3.4e38f;
            bi = 0x7FFFFFFF;
            for (int j = 0; j < ncand; j++) {
                int c = s_cand[w][j];
                const float* e = E + (size_t)c * 512;
                float sd = 0.f;
#pragma unroll
                for (int q = 0; q < 16; q++)
                    sd = fmaf(zc[q], e[lane + q * 32], sd);
#pragma unroll
                for (int ofs = 16; ofs > 0; ofs >>= 1)
                    sd += __shfl_xor_sync(0xffffffffu, sd, ofs);
                float t1 = zsq_m - 2.0f * sd;
                float d = t1 + g_esq[c];
                if (d < bd || (d == bd && c < bi)) { bd = d; bi = c; }
            }
        }
        if (lane == 0) {
            out[O_K + m] = (float)bi;
            int k1 = bi >> 5, k2 = bi & 31;
            s_code[w][0] = bi;                 s_mask[w][0] = 1.f;
            s_code[w][1] = (k1 + 1) * 32 + k2; s_mask[w][1] = (k1 < 31) ? 1.f : 0.f;
            s_code[w][2] = (k1 - 1) * 32 + k2; s_mask[w][2] = (k1 > 0)  ? 1.f : 0.f;
            s_code[w][3] = bi + 1;             s_mask[w][3] = (k2 < 31) ? 1.f : 0.f;
            s_code[w][4] = bi - 1;             s_mask[w][4] = (k2 > 0)  ? 1.f : 0.f;
        }
    }
    __syncthreads();

    // ---------------- phase 2: gather (R14-proven) ----------------
    int dq = tid & 255;
    int tg = tid >> 8;                     // 0..1, 8 t each
    float cacc = 0.f, sacc = 0.f;
    for (int i = 0; i < 8; i++) {
        int t = tg * 8 + i;
        int m = n * T_DIM + t0 + t;
        float2 ze = *(const float2*)(g_zt + (size_t)m * 512 + dq * 2);
        float* nbp = out + O_NB + (size_t)m * (5 * 512);
        float2 zq = *(const float2*)(E + (size_t)s_code[t][0] * 512 + dq * 2);
        __stcs((float2*)(nbp + dq * 2), zq);
        float dx = zq.x - ze.x, dy = zq.y - ze.y;
        cacc += dx * dx + dy * dy;
        sacc += dx * dx + dy * dy;
        *(float2*)&s[t * SG_STRIDE + dq * 2] = zq;
#pragma unroll
        for (int slot = 1; slot < 5; slot++) {
            float2 v;
            if (s_mask[t][slot] != 0.f)
                v = *(const float2*)(E + (size_t)s_code[t][slot] * 512 + dq * 2);
            else { v.x = 0.f; v.y = 0.f; }
            __stcs((float2*)(nbp + slot * 512 + dq * 2), v);
            float ax = ze.x - v.x, ay = ze.y - v.y;
            sacc += ax * ax + ay * ay;
        }
    }
    __syncthreads();

    // z_q_st[n, d, t0+4tq .. +3] float4 stores (16 t = 4 quads)
    {
        int tq = tid & 3;
        int dg = tid >> 2;                 // 0..127
        for (int d = dg; d < 512; d += 128) {
            float4 v;
            v.x = s[(4 * tq + 0) * SG_STRIDE + d];
            v.y = s[(4 * tq + 1) * SG_STRIDE + d];
            v.z = s[(4 * tq + 2) * SG_STRIDE + d];
            v.w = s[(4 * tq + 3) * SG_STRIDE + d];
            __stcs((float4*)&out[O_ZQST + (size_t)n * C_DIM * T_DIM
                                 + (size_t)d * T_DIM + t0 + 4 * tq], v);
        }
    }

    red[tid] = cacc;
    __syncthreads();
    for (int sft = 256; sft > 0; sft >>= 1) {
        if (tid < sft) red[tid] += red[tid + sft];
        __syncthreads();
    }
    float cblock = red[0];
    __syncthreads();
    red[tid] = sacc;
    __syncthreads();
    for (int sft = 256; sft > 0; sft >>= 1) {
        if (tid < sft) red[tid] += red[tid + sft];
        __syncthreads();
    }
    if (tid == 0) {
        int bid = blockIdx.y * gridDim.x + blockIdx.x;
        g_cpart[bid] = cblock;
        g_spart[bid] = red[0];
    }
}

__global__ void loss_kernel(float* __restrict__ out) {
    __shared__ double rc[256], rs[256];
    int tid = threadIdx.x;
    double c = 0.0, s = 0.0;
    for (int i = tid; i < NUM_GATHER_BLOCKS; i += 256) {
        c += (double)g_cpart[i];
        s += (double)g_spart[i];
    }
    rc[tid] = c; rs[tid] = s;
    __syncthreads();
    for (int sft = 128; sft > 0; sft >>= 1) {
        if (tid < sft) { rc[tid] += rc[tid + sft]; rs[tid] += rs[tid + sft]; }
        __syncthreads();
    }
    if (tid == 0) {
        double MD = (double)M_ROWS * (double)D_DIM;
        out[O_COMMIT] = (float)(2.0 * rc[0] / MD);
        out[O_SOM]    = (float)(rs[0] / (MD * 5.0));
    }
}

// ---------------------------------------------------------------------------
extern "C" void kernel_launch(void* const* d_in, const int* in_sizes, int n_in,
                              void* d_out, int out_size) {
    const float* x = (const float*)d_in[0];
    const float* E = (const float*)d_in[1];
    float* out = (float*)d_out;

    static int init = 0;
    if (!init) {
        cudaFuncSetAttribute(mma_dist_kernel,
                             cudaFuncAttributeMaxDynamicSharedMemorySize, DYN_SMEM);
        cudaFuncSetAttribute(gather_kernel,
                             cudaFuncAttributeMaxDynamicSharedMemorySize, GATHER_SMEM);
        init = 1;
    }

    dim3 gz(T_DIM / 32, C_DIM / 64, N_B);
    prep_z_kernel<<<gz, 256>>>(x);
    esq_zsq_kernel<<<K_CODES + M_ROWS / 256, 256>>>(E);
    dim3 gd(K_CODES / BN, M_ROWS / BM);
    mma_dist_kernel<<<gd, 256, DYN_SMEM>>>(out);
    dim3 g(T_DIM / 16, N_B);
    gather_kernel<<<g, 512, GATHER_SMEM>>>(E, out);
    loss_kernel<<<1, 256>>>(out);
}